// round 3
// baseline (speedup 1.0000x reference)
#include <cuda_runtime.h>
#include <math.h>

#define HID   2048
#define VOCAB 50257
#define NROWS (6 * HID)          // 12288 virtual rows (w_ih then w_hh)

// Scratch (no cudaMalloc allowed)
__device__ float        g_gi[3 * HID];
__device__ float        g_gh[3 * HID];
__device__ float        g_hnew[HID];
__device__ float        g_logits[VOCAB];
__device__ unsigned int g_max_u;
__device__ float        g_sum;
__device__ unsigned int g_count;      // softmax completion counter
__device__ unsigned int g_gemv_cnt;   // gate_gemv completion counter

// ---------------------------------------------------------------------------
// Kernel 1: GRU gate GEMVs, warp-per-row (the pattern that hits 90% of HBM).
// Virtual rows 0..6143  -> w_ih[row] . x      -> g_gi[row]
// Virtual rows 6144..   -> w_hh[row-6144] . h -> g_gh[row-6144]
// The LAST block to finish computes the gate math for all 2048 units and
// resets the softmax accumulators for this launch sequence.
// ---------------------------------------------------------------------------
__global__ void __launch_bounds__(256) gate_gemv_kernel(
    const int*   __restrict__ idx,
    const float* __restrict__ hidden,
    const float* __restrict__ embed,
    const float* __restrict__ w_ih,
    const float* __restrict__ w_hh,
    const float* __restrict__ b_ih,
    const float* __restrict__ b_hh,
    float*       __restrict__ hnew_out)   // may be null
{
    const int lane = threadIdx.x & 31;
    const int warp = threadIdx.x >> 5;
    const int vrow = blockIdx.x * 8 + warp;

    const int token = idx[0];

    const bool   is_ih = vrow < 3 * HID;
    const int    row   = is_ih ? vrow : vrow - 3 * HID;
    const float* wmat  = is_ih ? w_ih : w_hh;
    const float* vec   = is_ih ? (embed + (size_t)token * HID) : hidden;

    const float4* w4 = (const float4*)(wmat + (size_t)row * HID);
    const float4* v4 = (const float4*)vec;

    float acc = 0.0f;
    #pragma unroll
    for (int j = 0; j < 16; j++) {
        const int k = lane + 32 * j;
        const float4 w = w4[k];
        const float4 v = __ldg(&v4[k]);
        acc += w.x*v.x + w.y*v.y + w.z*v.z + w.w*v.w;
    }
    #pragma unroll
    for (int o = 16; o; o >>= 1)
        acc += __shfl_xor_sync(0xffffffffu, acc, o);

    if (lane == 0) {
        if (is_ih) g_gi[row] = acc;
        else       g_gh[row] = acc;
    }

    // --- last-block-done: final block runs the elementwise gate math ---
    __shared__ unsigned int s_last;
    __threadfence();
    __syncthreads();
    if (threadIdx.x == 0)
        s_last = (atomicAdd(&g_gemv_cnt, 1u) == gridDim.x - 1u) ? 1u : 0u;
    __syncthreads();

    if (s_last) {
        __threadfence();   // acquire: see all blocks' g_gi/g_gh stores
        #pragma unroll
        for (int j = 0; j < HID / 256; j++) {
            const int i = threadIdx.x + j * 256;
            const float gir = g_gi[i]         + b_ih[i];
            const float giz = g_gi[HID + i]   + b_ih[HID + i];
            const float gin = g_gi[2*HID + i] + b_ih[2*HID + i];
            const float ghr = g_gh[i]         + b_hh[i];
            const float ghz = g_gh[HID + i]   + b_hh[HID + i];
            const float ghn = g_gh[2*HID + i] + b_hh[2*HID + i];

            const float r  = 1.0f / (1.0f + expf(-(gir + ghr)));
            const float z  = 1.0f / (1.0f + expf(-(giz + ghz)));
            const float n  = tanhf(gin + r * ghn);
            const float hn = (1.0f - z) * n + z * hidden[i];

            g_hnew[i] = hn;
            if (hnew_out) hnew_out[i] = hn;
        }
        if (threadIdx.x == 0) {
            g_max_u    = 0u;
            g_sum      = 0.0f;
            g_count    = 0u;
            g_gemv_cnt = 0u;   // ready for next graph replay
        }
    }
}

// ---------------------------------------------------------------------------
// Kernel 2: logits = relu(w_out @ h_new + b_out). Warp-per-row, 8 rows/block.
// Tracks the global max via atomicMax on uint bits (valid: all values >= 0).
// ---------------------------------------------------------------------------
__global__ void __launch_bounds__(256) logits_kernel(
    const float* __restrict__ w_out,
    const float* __restrict__ b_out)
{
    const int lane = threadIdx.x & 31;
    const int warp = threadIdx.x >> 5;
    const int row  = blockIdx.x * 8 + warp;

    float l = 0.0f;
    if (row < VOCAB) {
        const float4* w4 = (const float4*)(w_out + (size_t)row * HID);
        const float4* h4 = (const float4*)g_hnew;
        float acc = 0.0f;
        #pragma unroll
        for (int j = 0; j < 16; j++) {
            const int k = lane + 32 * j;
            const float4 w = w4[k];
            const float4 h = h4[k];
            acc += w.x*h.x + w.y*h.y + w.z*h.z + w.w*h.w;
        }
        #pragma unroll
        for (int o = 16; o; o >>= 1)
            acc += __shfl_xor_sync(0xffffffffu, acc, o);
        l = fmaxf(acc + b_out[row], 0.0f);
        if (lane == 0) g_logits[row] = l;
    }

    __shared__ float smax[8];
    if (lane == 0) smax[warp] = l;
    __syncthreads();
    if (threadIdx.x == 0) {
        float m = smax[0];
        #pragma unroll
        for (int w = 1; w < 8; w++) m = fmaxf(m, smax[w]);
        atomicMax(&g_max_u, __float_as_uint(m));   // all values >= 0
    }
}

// ---------------------------------------------------------------------------
// Kernel 3: fused sum-exp + finalize. ONE wave (148 blocks x 256): partial
// sums -> atomicAdd -> completion-counter spin -> write outputs from regs.
// Safe: grid <= 1 block/SM, so all blocks are co-resident.
// ---------------------------------------------------------------------------
#define NBLK 148
#define ELEMS_PER_THREAD 2   // ceil(50257 / (148*256)) = 2

__global__ void __launch_bounds__(256) softmax_kernel(float* __restrict__ out)
{
    const int tid    = threadIdx.x;
    const int stride = NBLK * 256;
    const float m    = __uint_as_float(g_max_u);

    float lv[ELEMS_PER_THREAD];
    int   vi[ELEMS_PER_THREAD];
    float s = 0.0f;

    #pragma unroll
    for (int j = 0; j < ELEMS_PER_THREAD; j++) {
        const int v = blockIdx.x * 256 + tid + j * stride;
        vi[j] = v;
        if (v < VOCAB) {
            const float l = g_logits[v];
            lv[j] = l;
            s += expf(l - m);
        }
    }

    #pragma unroll
    for (int o = 16; o; o >>= 1)
        s += __shfl_xor_sync(0xffffffffu, s, o);

    __shared__ float sh[8];
    const int lane = tid & 31;
    const int warp = tid >> 5;
    if (lane == 0) sh[warp] = s;
    __syncthreads();

    if (tid == 0) {
        float t = sh[0];
        #pragma unroll
        for (int w = 1; w < 8; w++) t += sh[w];
        atomicAdd(&g_sum, t);
        __threadfence();
        atomicAdd(&g_count, 1u);
        volatile unsigned int* cnt = &g_count;
        while (*cnt < (unsigned int)gridDim.x) { __nanosleep(64); }
        __threadfence();
        sh[0] = logf(g_sum);
    }
    __syncthreads();

    const float logsum = sh[0];
    #pragma unroll
    for (int j = 0; j < ELEMS_PER_THREAD; j++) {
        if (vi[j] < VOCAB)
            out[vi[j]] = lv[j] - m - logsum;
    }
}

// ---------------------------------------------------------------------------
extern "C" void kernel_launch(void* const* d_in, const int* in_sizes, int n_in,
                              void* d_out, int out_size)
{
    const int*   idx    = (const int*)  d_in[0];
    const float* hidden = (const float*)d_in[1];
    const float* embed  = (const float*)d_in[2];
    const float* w_ih   = (const float*)d_in[3];
    const float* w_hh   = (const float*)d_in[4];
    const float* b_ih   = (const float*)d_in[5];
    const float* b_hh   = (const float*)d_in[6];
    const float* w_out  = (const float*)d_in[7];
    const float* b_out  = (const float*)d_in[8];

    float* out = (float*)d_out;
    float* hnew_out = (out_size >= VOCAB + HID) ? (out + VOCAB) : nullptr;

    gate_gemv_kernel<<<NROWS / 8, 256>>>(idx, hidden, embed, w_ih, w_hh,
                                         b_ih, b_hh, hnew_out);
    logits_kernel<<<(VOCAB + 7) / 8, 256>>>(w_out, b_out);
    softmax_kernel<<<NBLK, 256>>>(out);
}

// round 4
// speedup vs baseline: 1.0010x; 1.0010x over previous
#include <cuda_runtime.h>
#include <math.h>

#define HID   2048
#define VOCAB 50257
#define NROWS (6 * HID)          // 12288 virtual rows (w_ih then w_hh)

// Scratch (no cudaMalloc allowed)
__device__ float        g_gi[3 * HID];
__device__ float        g_gh[3 * HID];
__device__ float        g_hnew[HID];
__device__ float        g_logits[VOCAB];
__device__ unsigned int g_max_u;
__device__ float        g_sum;
__device__ unsigned int g_count;      // softmax completion counter
__device__ unsigned int g_gemv_cnt;   // gate_gemv completion counter

// ---------------------------------------------------------------------------
// Kernel 1: GRU gate GEMVs, warp-per-row.
// Virtual rows 0..6143  -> w_ih[row] . x      -> g_gi[row]
// Virtual rows 6144..   -> w_hh[row-6144] . h -> g_gh[row-6144]
// Publication: ONE fence per block (tid 0 only). The LAST block to arrive
// runs the elementwise gate math and resets the softmax accumulators.
// ---------------------------------------------------------------------------
__global__ void __launch_bounds__(256) gate_gemv_kernel(
    const int*   __restrict__ idx,
    const float* __restrict__ hidden,
    const float* __restrict__ embed,
    const float* __restrict__ w_ih,
    const float* __restrict__ w_hh,
    const float* __restrict__ b_ih,
    const float* __restrict__ b_hh,
    float*       __restrict__ hnew_out)   // may be null
{
    const int lane = threadIdx.x & 31;
    const int warp = threadIdx.x >> 5;
    const int vrow = blockIdx.x * 8 + warp;

    const int token = idx[0];

    const bool   is_ih = vrow < 3 * HID;
    const int    row   = is_ih ? vrow : vrow - 3 * HID;
    const float* wmat  = is_ih ? w_ih : w_hh;
    const float* vec   = is_ih ? (embed + (size_t)token * HID) : hidden;

    const float4* w4 = (const float4*)(wmat + (size_t)row * HID);
    const float4* v4 = (const float4*)vec;

    float acc = 0.0f;
    #pragma unroll
    for (int j = 0; j < 16; j++) {
        const int k = lane + 32 * j;
        const float4 w = w4[k];
        const float4 v = __ldg(&v4[k]);
        acc += w.x*v.x + w.y*v.y + w.z*v.z + w.w*v.w;
    }
    #pragma unroll
    for (int o = 16; o; o >>= 1)
        acc += __shfl_xor_sync(0xffffffffu, acc, o);

    if (lane == 0) {
        if (is_ih) g_gi[row] = acc;
        else       g_gh[row] = acc;
    }

    // --- last-block-done: single release fence per block (tid 0 only) ---
    __shared__ unsigned int s_last;
    __syncthreads();                       // orders lane-0 stores before tid-0
    if (threadIdx.x == 0) {
        __threadfence();                   // release our block's stores
        s_last = (atomicAdd(&g_gemv_cnt, 1u) == gridDim.x - 1u) ? 1u : 0u;
    }
    __syncthreads();

    if (s_last) {
        __threadfence();   // acquire: see all other blocks' g_gi/g_gh stores
        #pragma unroll
        for (int j = 0; j < HID / 256; j++) {
            const int i = threadIdx.x + j * 256;
            const float gir = g_gi[i]         + b_ih[i];
            const float giz = g_gi[HID + i]   + b_ih[HID + i];
            const float gin = g_gi[2*HID + i] + b_ih[2*HID + i];
            const float ghr = g_gh[i]         + b_hh[i];
            const float ghz = g_gh[HID + i]   + b_hh[HID + i];
            const float ghn = g_gh[2*HID + i] + b_hh[2*HID + i];

            const float r  = 1.0f / (1.0f + expf(-(gir + ghr)));
            const float z  = 1.0f / (1.0f + expf(-(giz + ghz)));
            const float n  = tanhf(gin + r * ghn);
            const float hn = (1.0f - z) * n + z * hidden[i];

            g_hnew[i] = hn;
            if (hnew_out) hnew_out[i] = hn;
        }
        if (threadIdx.x == 0) {
            g_max_u    = 0u;
            g_sum      = 0.0f;
            g_count    = 0u;
            g_gemv_cnt = 0u;   // ready for next graph replay
        }
    }
}

// ---------------------------------------------------------------------------
// Kernel 2: logits = relu(w_out @ h_new + b_out). Warp-per-row, 8 rows/block.
// Tracks the global max via atomicMax on uint bits (valid: all values >= 0).
// ---------------------------------------------------------------------------
__global__ void __launch_bounds__(256) logits_kernel(
    const float* __restrict__ w_out,
    const float* __restrict__ b_out)
{
    const int lane = threadIdx.x & 31;
    const int warp = threadIdx.x >> 5;
    const int row  = blockIdx.x * 8 + warp;

    float l = 0.0f;
    if (row < VOCAB) {
        const float4* w4 = (const float4*)(w_out + (size_t)row * HID);
        const float4* h4 = (const float4*)g_hnew;
        float acc = 0.0f;
        #pragma unroll
        for (int j = 0; j < 16; j++) {
            const int k = lane + 32 * j;
            const float4 w = w4[k];
            const float4 h = h4[k];
            acc += w.x*h.x + w.y*h.y + w.z*h.z + w.w*h.w;
        }
        #pragma unroll
        for (int o = 16; o; o >>= 1)
            acc += __shfl_xor_sync(0xffffffffu, acc, o);
        l = fmaxf(acc + b_out[row], 0.0f);
        if (lane == 0) g_logits[row] = l;
    }

    __shared__ float smax[8];
    if (lane == 0) smax[warp] = l;
    __syncthreads();
    if (threadIdx.x == 0) {
        float m = smax[0];
        #pragma unroll
        for (int w = 1; w < 8; w++) m = fmaxf(m, smax[w]);
        atomicMax(&g_max_u, __float_as_uint(m));   // all values >= 0
    }
}

// ---------------------------------------------------------------------------
// Kernel 3: fused sum-exp + finalize. ONE wave (148 blocks x 256): partial
// sums -> atomicAdd -> completion-counter spin -> write outputs from regs.
// Safe: grid <= 1 block/SM, so all blocks are co-resident.
// ---------------------------------------------------------------------------
#define NBLK 148
#define ELEMS_PER_THREAD 2   // ceil(50257 / (148*256)) = 2

__global__ void __launch_bounds__(256) softmax_kernel(float* __restrict__ out)
{
    const int tid    = threadIdx.x;
    const int stride = NBLK * 256;
    const float m    = __uint_as_float(g_max_u);

    float lv[ELEMS_PER_THREAD];
    int   vi[ELEMS_PER_THREAD];
    float s = 0.0f;

    #pragma unroll
    for (int j = 0; j < ELEMS_PER_THREAD; j++) {
        const int v = blockIdx.x * 256 + tid + j * stride;
        vi[j] = v;
        if (v < VOCAB) {
            const float l = g_logits[v];
            lv[j] = l;
            s += expf(l - m);
        }
    }

    #pragma unroll
    for (int o = 16; o; o >>= 1)
        s += __shfl_xor_sync(0xffffffffu, s, o);

    __shared__ float sh[8];
    const int lane = tid & 31;
    const int warp = tid >> 5;
    if (lane == 0) sh[warp] = s;
    __syncthreads();

    if (tid == 0) {
        float t = sh[0];
        #pragma unroll
        for (int w = 1; w < 8; w++) t += sh[w];
        atomicAdd(&g_sum, t);
        __threadfence();
        atomicAdd(&g_count, 1u);
        volatile unsigned int* cnt = &g_count;
        while (*cnt < (unsigned int)gridDim.x) { __nanosleep(64); }
        __threadfence();
        sh[0] = logf(g_sum);
    }
    __syncthreads();

    const float logsum = sh[0];
    #pragma unroll
    for (int j = 0; j < ELEMS_PER_THREAD; j++) {
        if (vi[j] < VOCAB)
            out[vi[j]] = lv[j] - m - logsum;
    }
}

// ---------------------------------------------------------------------------
extern "C" void kernel_launch(void* const* d_in, const int* in_sizes, int n_in,
                              void* d_out, int out_size)
{
    const int*   idx    = (const int*)  d_in[0];
    const float* hidden = (const float*)d_in[1];
    const float* embed  = (const float*)d_in[2];
    const float* w_ih   = (const float*)d_in[3];
    const float* w_hh   = (const float*)d_in[4];
    const float* b_ih   = (const float*)d_in[5];
    const float* b_hh   = (const float*)d_in[6];
    const float* w_out  = (const float*)d_in[7];
    const float* b_out  = (const float*)d_in[8];

    float* out = (float*)d_out;
    float* hnew_out = (out_size >= VOCAB + HID) ? (out + VOCAB) : nullptr;

    gate_gemv_kernel<<<NROWS / 8, 256>>>(idx, hidden, embed, w_ih, w_hh,
                                         b_ih, b_hh, hnew_out);
    logits_kernel<<<(VOCAB + 7) / 8, 256>>>(w_out, b_out);
    softmax_kernel<<<NBLK, 256>>>(out);
}

// round 5
// speedup vs baseline: 1.0385x; 1.0375x over previous
#include <cuda_runtime.h>
#include <math.h>

#define HID   2048
#define VOCAB 50257
#define NROWS (6 * HID)          // 12288 virtual rows (w_ih then w_hh)
#define IH_BLOCKS 768            // blocks 0..767 -> w_ih, 768..1535 -> w_hh

// Scratch (no cudaMalloc allowed)
__device__ float        g_gi[3 * HID];
__device__ float        g_gh[3 * HID];
__device__ float        g_hnew[HID];
__device__ float        g_logits[VOCAB];
__device__ unsigned int g_max_u;
__device__ float        g_sum;
__device__ unsigned int g_count;      // softmax completion counter
__device__ unsigned int g_gemv_cnt;   // gate_gemv completion counter

// ---------------------------------------------------------------------------
// Kernel 1: GRU gate GEMVs, warp-per-row, vector staged in shared memory.
// Block b < 768 : rows 8b..8b+7 of w_ih . x   -> g_gi
// Block b >= 768: rows of w_hh . h            -> g_gh
// Weight loads explicitly batched 8-wide for high MLP. The LAST block to
// arrive computes the elementwise gate math and resets softmax accumulators.
// ---------------------------------------------------------------------------
__global__ void __launch_bounds__(256) gate_gemv_kernel(
    const int*   __restrict__ idx,
    const float* __restrict__ hidden,
    const float* __restrict__ embed,
    const float* __restrict__ w_ih,
    const float* __restrict__ w_hh,
    const float* __restrict__ b_ih,
    const float* __restrict__ b_hh,
    float*       __restrict__ hnew_out)   // may be null
{
    __shared__ float4 s_vec[HID / 4];     // 8 KB staged vector
    __shared__ unsigned int s_last;

    const int tid  = threadIdx.x;
    const int lane = tid & 31;
    const int warp = tid >> 5;

    const bool is_ih = blockIdx.x < IH_BLOCKS;
    const int  row   = (is_ih ? blockIdx.x : blockIdx.x - IH_BLOCKS) * 8 + warp;

    // Stage the shared vector (x = embed row, or h) into smem: 2 ld/thread.
    {
        const int token = idx[0];
        const float4* v4 = (const float4*)(is_ih ? (embed + (size_t)token * HID)
                                                 : hidden);
        const float4 a = v4[tid];
        const float4 b = v4[tid + 256];
        s_vec[tid]       = a;
        s_vec[tid + 256] = b;
    }
    __syncthreads();

    // Warp-per-row dot product, weight loads batched 8 at a time.
    {
        const float4* w4 = (const float4*)((is_ih ? w_ih : w_hh) + (size_t)row * HID);
        float acc = 0.0f;
        float4 wr[8];

        #pragma unroll
        for (int half = 0; half < 2; half++) {
            const int base = lane + half * 256;
            #pragma unroll
            for (int j = 0; j < 8; j++) wr[j] = w4[base + 32 * j];
            #pragma unroll
            for (int j = 0; j < 8; j++) {
                const float4 v = s_vec[base + 32 * j];
                acc += wr[j].x*v.x + wr[j].y*v.y + wr[j].z*v.z + wr[j].w*v.w;
            }
        }

        #pragma unroll
        for (int o = 16; o; o >>= 1)
            acc += __shfl_xor_sync(0xffffffffu, acc, o);

        if (lane == 0) {
            if (is_ih) g_gi[row] = acc;
            else       g_gh[row] = acc;
        }
    }

    // --- last-block-done: single release fence per block (tid 0 only) ---
    __syncthreads();                       // orders lane-0 stores before tid-0
    if (tid == 0) {
        __threadfence();                   // release this block's stores
        s_last = (atomicAdd(&g_gemv_cnt, 1u) == gridDim.x - 1u) ? 1u : 0u;
    }
    __syncthreads();

    if (s_last) {
        __threadfence();   // acquire: see all other blocks' g_gi/g_gh stores
        #pragma unroll
        for (int j = 0; j < HID / 256; j++) {
            const int i = tid + j * 256;
            const float gir = g_gi[i]         + b_ih[i];
            const float giz = g_gi[HID + i]   + b_ih[HID + i];
            const float gin = g_gi[2*HID + i] + b_ih[2*HID + i];
            const float ghr = g_gh[i]         + b_hh[i];
            const float ghz = g_gh[HID + i]   + b_hh[HID + i];
            const float ghn = g_gh[2*HID + i] + b_hh[2*HID + i];

            const float r  = 1.0f / (1.0f + expf(-(gir + ghr)));
            const float z  = 1.0f / (1.0f + expf(-(giz + ghz)));
            const float n  = tanhf(gin + r * ghn);
            const float hn = (1.0f - z) * n + z * hidden[i];

            g_hnew[i] = hn;
            if (hnew_out) hnew_out[i] = hn;
        }
        if (tid == 0) {
            g_max_u    = 0u;
            g_sum      = 0.0f;
            g_count    = 0u;
            g_gemv_cnt = 0u;   // ready for next graph replay
        }
    }
}

// ---------------------------------------------------------------------------
// Kernel 2: logits = relu(w_out @ h_new + b_out). Warp-per-row, 8 rows/block.
// Tracks the global max via atomicMax on uint bits (valid: all values >= 0).
// ---------------------------------------------------------------------------
__global__ void __launch_bounds__(256) logits_kernel(
    const float* __restrict__ w_out,
    const float* __restrict__ b_out)
{
    const int lane = threadIdx.x & 31;
    const int warp = threadIdx.x >> 5;
    const int row  = blockIdx.x * 8 + warp;

    float l = 0.0f;
    if (row < VOCAB) {
        const float4* w4 = (const float4*)(w_out + (size_t)row * HID);
        const float4* h4 = (const float4*)g_hnew;
        float acc = 0.0f;
        #pragma unroll
        for (int j = 0; j < 16; j++) {
            const int k = lane + 32 * j;
            const float4 w = w4[k];
            const float4 h = h4[k];
            acc += w.x*h.x + w.y*h.y + w.z*h.z + w.w*h.w;
        }
        #pragma unroll
        for (int o = 16; o; o >>= 1)
            acc += __shfl_xor_sync(0xffffffffu, acc, o);
        l = fmaxf(acc + b_out[row], 0.0f);
        if (lane == 0) g_logits[row] = l;
    }

    __shared__ float smax[8];
    if (lane == 0) smax[warp] = l;
    __syncthreads();
    if (threadIdx.x == 0) {
        float m = smax[0];
        #pragma unroll
        for (int w = 1; w < 8; w++) m = fmaxf(m, smax[w]);
        atomicMax(&g_max_u, __float_as_uint(m));   // all values >= 0
    }
}

// ---------------------------------------------------------------------------
// Kernel 3: fused sum-exp + finalize. ONE wave (148 blocks x 256): partial
// sums -> atomicAdd -> completion-counter spin -> write outputs from regs.
// Safe: grid <= 1 block/SM, so all blocks are co-resident.
// ---------------------------------------------------------------------------
#define NBLK 148
#define ELEMS_PER_THREAD 2   // ceil(50257 / (148*256)) = 2

__global__ void __launch_bounds__(256) softmax_kernel(float* __restrict__ out)
{
    const int tid    = threadIdx.x;
    const int stride = NBLK * 256;
    const float m    = __uint_as_float(g_max_u);

    float lv[ELEMS_PER_THREAD];
    int   vi[ELEMS_PER_THREAD];
    float s = 0.0f;

    #pragma unroll
    for (int j = 0; j < ELEMS_PER_THREAD; j++) {
        const int v = blockIdx.x * 256 + tid + j * stride;
        vi[j] = v;
        if (v < VOCAB) {
            const float l = g_logits[v];
            lv[j] = l;
            s += expf(l - m);
        }
    }

    #pragma unroll
    for (int o = 16; o; o >>= 1)
        s += __shfl_xor_sync(0xffffffffu, s, o);

    __shared__ float sh[8];
    const int lane = tid & 31;
    const int warp = tid >> 5;
    if (lane == 0) sh[warp] = s;
    __syncthreads();

    if (tid == 0) {
        float t = sh[0];
        #pragma unroll
        for (int w = 1; w < 8; w++) t += sh[w];
        atomicAdd(&g_sum, t);
        __threadfence();
        atomicAdd(&g_count, 1u);
        volatile unsigned int* cnt = &g_count;
        while (*cnt < (unsigned int)gridDim.x) { __nanosleep(64); }
        __threadfence();
        sh[0] = logf(g_sum);
    }
    __syncthreads();

    const float logsum = sh[0];
    #pragma unroll
    for (int j = 0; j < ELEMS_PER_THREAD; j++) {
        if (vi[j] < VOCAB)
            out[vi[j]] = lv[j] - m - logsum;
    }
}

// ---------------------------------------------------------------------------
extern "C" void kernel_launch(void* const* d_in, const int* in_sizes, int n_in,
                              void* d_out, int out_size)
{
    const int*   idx    = (const int*)  d_in[0];
    const float* hidden = (const float*)d_in[1];
    const float* embed  = (const float*)d_in[2];
    const float* w_ih   = (const float*)d_in[3];
    const float* w_hh   = (const float*)d_in[4];
    const float* b_ih   = (const float*)d_in[5];
    const float* b_hh   = (const float*)d_in[6];
    const float* w_out  = (const float*)d_in[7];
    const float* b_out  = (const float*)d_in[8];

    float* out = (float*)d_out;
    float* hnew_out = (out_size >= VOCAB + HID) ? (out + VOCAB) : nullptr;

    gate_gemv_kernel<<<NROWS / 8, 256>>>(idx, hidden, embed, w_ih, w_hh,
                                         b_ih, b_hh, hnew_out);
    logits_kernel<<<(VOCAB + 7) / 8, 256>>>(w_out, b_out);
    softmax_kernel<<<NBLK, 256>>>(out);
}